// round 3
// baseline (speedup 1.0000x reference)
#include <cuda_runtime.h>
#include <math.h>

#define BATCH 8
#define QLEN 256
#define KLEN 1024
#define DQ   256
#define DV   128
#define H    128

// Scratch (statically allocated device globals — no cudaMalloc).
__device__ float g_qh[BATCH * QLEN * H];          // 1 MB
__device__ float g_kh[BATCH * KLEN * H];          // 4 MB
__device__ float g_sc[BATCH * QLEN * KLEN];       // 8 MB

__device__ __forceinline__ float fast_tanh(float x) {
    float y;
    asm("tanh.approx.f32 %0, %1;" : "=f"(y) : "f"(x));
    return y;
}

// ---------------------------------------------------------------------------
// Kernel 1: fused projections qh = Q@Wq, kh = K@Wk.
// Block = 64 output rows x 128 cols (full H). 256 threads, 8x4 reg tile each.
// ---------------------------------------------------------------------------
__global__ __launch_bounds__(256) void proj_kernel(
    const float* __restrict__ Qin, const float* __restrict__ Kin,
    const float* __restrict__ Wq,  const float* __restrict__ Wk)
{
    __shared__ float Xs[32][64];    // [d][row]
    __shared__ float Ws[32][128];   // [d][col]

    int blk = blockIdx.x;
    const float* X; const float* W; float* Y; int r0;
    if (blk < 32) { X = Qin; W = Wq; Y = g_qh; r0 = blk * 64; }
    else          { X = Kin; W = Wk; Y = g_kh; r0 = (blk - 32) * 64; }

    int tid = threadIdx.x;
    int tx = tid & 31;       // -> 4 cols at 4*tx
    int ty = tid >> 5;       // -> 8 rows at 8*ty

    float acc[8][4];
    #pragma unroll
    for (int i = 0; i < 8; i++) { acc[i][0] = acc[i][1] = acc[i][2] = acc[i][3] = 0.f; }

    for (int d0 = 0; d0 < DQ; d0 += 32) {
        // Stage X tile transposed: Xs[dd][r]
        #pragma unroll
        for (int it = 0; it < 2; it++) {
            int i = tid + it * 256;          // 0..511
            int r = i >> 3, dv = (i & 7) << 2;
            float4 v = *(const float4*)(X + (size_t)(r0 + r) * DQ + d0 + dv);
            Xs[dv + 0][r] = v.x; Xs[dv + 1][r] = v.y;
            Xs[dv + 2][r] = v.z; Xs[dv + 3][r] = v.w;
        }
        // Stage W tile direct: Ws[dd][c]
        #pragma unroll
        for (int it = 0; it < 4; it++) {
            int i = tid + it * 256;          // 0..1023
            int dd = i >> 5, c = (i & 31) << 2;
            *(float4*)&Ws[dd][c] = *(const float4*)(W + (size_t)(d0 + dd) * H + c);
        }
        __syncthreads();

        #pragma unroll 4
        for (int dd = 0; dd < 32; dd++) {
            float4 wv = *(const float4*)&Ws[dd][tx << 2];
            float4 xa = *(const float4*)&Xs[dd][ty << 3];
            float4 xb = *(const float4*)&Xs[dd][(ty << 3) + 4];
            float xs[8] = {xa.x, xa.y, xa.z, xa.w, xb.x, xb.y, xb.z, xb.w};
            #pragma unroll
            for (int i = 0; i < 8; i++) {
                acc[i][0] = fmaf(xs[i], wv.x, acc[i][0]);
                acc[i][1] = fmaf(xs[i], wv.y, acc[i][1]);
                acc[i][2] = fmaf(xs[i], wv.z, acc[i][2]);
                acc[i][3] = fmaf(xs[i], wv.w, acc[i][3]);
            }
        }
        __syncthreads();
    }

    #pragma unroll
    for (int i = 0; i < 8; i++) {
        float4 v = make_float4(acc[i][0], acc[i][1], acc[i][2], acc[i][3]);
        *(float4*)(Y + (size_t)(r0 + (ty << 3) + i) * H + (tx << 2)) = v;
    }
}

// ---------------------------------------------------------------------------
// Kernel 2: scores[b,q,k] = sum_h w[h] * tanh(qh[b,q,h] + kh[b,k,h])
// Block = 64 q x 64 k tile; grid (ktile=16, qtile=4, b=8).
// Early-exit entire K-tiles beyond valid_len (exp underflows to exact 0 in
// the reference, so these scores are never needed).
// 256 threads, each a 4x4 (q,k) register tile; h staged in chunks of 32.
// MUFU-bound by design: per tanh exactly 1 FADD + 1 FFMA, LDS amortized 8x.
// ---------------------------------------------------------------------------
__global__ __launch_bounds__(256) void scores_kernel(
    const float* __restrict__ wv_g, const int* __restrict__ valid)
{
    __shared__ float qs[32][64];    // [h][q]
    __shared__ float ks[32][64];    // [h][k]
    __shared__ float wvs[H];

    int b  = blockIdx.z;
    int vl = valid[b];
    int k0 = blockIdx.x * 64;
    if (k0 >= vl) return;
    int q0 = blockIdx.y * 64;

    int tid = threadIdx.x;
    if (tid < H) wvs[tid] = wv_g[tid];

    int tx = tid & 15;      // k sub-tile: 4 keys at 4*tx
    int ty = tid >> 4;      // q sub-tile: 4 queries at 4*ty

    float acc[4][4] = {};
    const float* qbase = g_qh + ((size_t)b * QLEN + q0) * H;
    const float* kbase = g_kh + ((size_t)b * KLEN + k0) * H;

    for (int h0 = 0; h0 < H; h0 += 32) {
        __syncthreads();   // previous compute done (and wvs visible on iter 0)
        #pragma unroll
        for (int it = 0; it < 2; it++) {
            int i = tid + it * 256;          // 0..511
            int r = i >> 3, hv = (i & 7) << 2;
            float4 v = *(const float4*)(qbase + (size_t)r * H + h0 + hv);
            qs[hv + 0][r] = v.x; qs[hv + 1][r] = v.y;
            qs[hv + 2][r] = v.z; qs[hv + 3][r] = v.w;
            float4 u = *(const float4*)(kbase + (size_t)r * H + h0 + hv);
            ks[hv + 0][r] = u.x; ks[hv + 1][r] = u.y;
            ks[hv + 2][r] = u.z; ks[hv + 3][r] = u.w;
        }
        __syncthreads();

        #pragma unroll 4
        for (int hh = 0; hh < 32; hh++) {
            float w = wvs[h0 + hh];
            float4 qv = *(const float4*)&qs[hh][ty << 2];
            float4 kv = *(const float4*)&ks[hh][tx << 2];
            float qa[4] = {qv.x, qv.y, qv.z, qv.w};
            float ka[4] = {kv.x, kv.y, kv.z, kv.w};
            #pragma unroll
            for (int i = 0; i < 4; i++) {
                #pragma unroll
                for (int j = 0; j < 4; j++) {
                    acc[i][j] = fmaf(w, fast_tanh(qa[i] + ka[j]), acc[i][j]);
                }
            }
        }
    }

    float* srow = g_sc + ((size_t)b * QLEN + q0 + (ty << 2)) * KLEN + k0 + (tx << 2);
    #pragma unroll
    for (int i = 0; i < 4; i++) {
        *(float4*)(srow + (size_t)i * KLEN) =
            make_float4(acc[i][0], acc[i][1], acc[i][2], acc[i][3]);
    }
}

// ---------------------------------------------------------------------------
// Kernel 3: per (b,q) row masked softmax over k<valid_len, then attn @ V.
// 128 threads: 32 lanes x float4 over Dv=128, 4-way split over k.
// ---------------------------------------------------------------------------
__global__ __launch_bounds__(128) void softmax_av_kernel(
    const float* __restrict__ values, const int* __restrict__ valid,
    float* __restrict__ out)
{
    __shared__ float  p[KLEN];
    __shared__ float  red[4];
    __shared__ float4 accs[128];

    int bq  = blockIdx.x;
    int b   = bq >> 8;
    int vl  = valid[b];
    int tid = threadIdx.x;
    const float* srow = g_sc + (size_t)bq * KLEN;

    // --- max over valid scores ---
    float m = -3.0e38f;
    for (int k = tid; k < vl; k += 128) m = fmaxf(m, srow[k]);
    #pragma unroll
    for (int o = 16; o; o >>= 1) m = fmaxf(m, __shfl_xor_sync(0xffffffffu, m, o));
    if ((tid & 31) == 0) red[tid >> 5] = m;
    __syncthreads();
    m = fmaxf(fmaxf(red[0], red[1]), fmaxf(red[2], red[3]));

    // --- exp + sum ---
    float l = 0.f;
    for (int k = tid; k < vl; k += 128) {
        float e = __expf(srow[k] - m);
        p[k] = e;
        l += e;
    }
    #pragma unroll
    for (int o = 16; o; o >>= 1) l += __shfl_xor_sync(0xffffffffu, l, o);
    __syncthreads();                 // p[] visible; red[] reads from max done
    if ((tid & 31) == 0) red[tid >> 5] = l;
    __syncthreads();
    l = (red[0] + red[1]) + (red[2] + red[3]);
    float inv = 1.0f / l;

    // --- attn @ V ---
    int vg = tid & 31;               // 4 v-columns at 4*vg
    int kg = tid >> 5;               // 4-way k split
    const float* vbase = values + (size_t)b * KLEN * DV + (vg << 2);
    float4 a = make_float4(0.f, 0.f, 0.f, 0.f);
    for (int k = kg; k < vl; k += 4) {
        float pk = p[k];
        float4 vv = *(const float4*)(vbase + (size_t)k * DV);
        a.x = fmaf(pk, vv.x, a.x);
        a.y = fmaf(pk, vv.y, a.y);
        a.z = fmaf(pk, vv.z, a.z);
        a.w = fmaf(pk, vv.w, a.w);
    }
    accs[tid] = a;
    __syncthreads();
    if (tid < 32) {
        float4 r = accs[tid];
        #pragma unroll
        for (int g = 1; g < 4; g++) {
            float4 t = accs[g * 32 + tid];
            r.x += t.x; r.y += t.y; r.z += t.z; r.w += t.w;
        }
        r.x *= inv; r.y *= inv; r.z *= inv; r.w *= inv;
        *(float4*)(out + (size_t)bq * DV + (tid << 2)) = r;
    }
}

// ---------------------------------------------------------------------------
extern "C" void kernel_launch(void* const* d_in, const int* in_sizes, int n_in,
                              void* d_out, int out_size)
{
    const float* queries = (const float*)d_in[0];
    const float* keys    = (const float*)d_in[1];
    const float* values  = (const float*)d_in[2];
    const int*   valid   = (const int*)d_in[3];
    const float* Wq      = (const float*)d_in[4];
    const float* Wk      = (const float*)d_in[5];
    const float* wv      = (const float*)d_in[6];
    float* out = (float*)d_out;

    proj_kernel<<<160, 256>>>(queries, keys, Wq, Wk);
    scores_kernel<<<dim3(16, 4, 8), 256>>>(wv, valid);
    softmax_av_kernel<<<BATCH * QLEN, 128>>>(values, valid, out);
}

// round 4
// speedup vs baseline: 1.5412x; 1.5412x over previous
#include <cuda_runtime.h>
#include <math.h>

#define BATCH 8
#define QLEN 256
#define KLEN 1024
#define DQ   256
#define DV   128
#define H    128

// Scratch (statically allocated device globals — no cudaMalloc).
__device__ float g_qh[BATCH * QLEN * H];          // 1 MB
__device__ float g_kh[BATCH * KLEN * H];          // 4 MB
__device__ float g_sc[BATCH * QLEN * KLEN];       // 8 MB
__device__ unsigned int g_ctr;                    // work-stealing counter

__device__ __forceinline__ float fast_tanh(float x) {
    float y;
    asm("tanh.approx.f32 %0, %1;" : "=f"(y) : "f"(x));
    return y;
}

// ---------------------------------------------------------------------------
// Kernel 1: fused projections qh = Q@Wq, kh = K@Wk.
// 32 output rows x 128 cols per block -> 320 blocks (~2 CTAs/SM).
// 256 threads, 4x4 register tile each. Also resets the scores work counter.
// ---------------------------------------------------------------------------
__global__ __launch_bounds__(256) void proj_kernel(
    const float* __restrict__ Qin, const float* __restrict__ Kin,
    const float* __restrict__ Wq,  const float* __restrict__ Wk)
{
    if (blockIdx.x == 0 && threadIdx.x == 0) g_ctr = 0;  // reset for scores

    __shared__ float Xs[32][36];    // [row][d] (pad keeps 16B align, spreads banks)
    __shared__ float Ws[32][128];   // [d][col]

    int blk = blockIdx.x;
    const float* X; const float* W; float* Y; int r0;
    if (blk < 64) { X = Qin; W = Wq; Y = g_qh; r0 = blk * 32; }
    else          { X = Kin; W = Wk; Y = g_kh; r0 = (blk - 64) * 32; }

    int tid = threadIdx.x;
    int tx = tid & 31;       // -> 4 cols at 4*tx
    int ty = tid >> 5;       // -> 4 rows at 4*ty

    float acc[4][4] = {};

    for (int d0 = 0; d0 < DQ; d0 += 32) {
        // Stage X tile: 32 rows x 32 d (direct float4 copy)
        {
            int r = tid >> 3, dv = (tid & 7) << 2;
            float4 v = *(const float4*)(X + (size_t)(r0 + r) * DQ + d0 + dv);
            *(float4*)&Xs[r][dv] = v;
        }
        // Stage W tile: 32 d x 128 cols
        #pragma unroll
        for (int it = 0; it < 4; it++) {
            int i = tid + it * 256;          // 0..1023
            int dd = i >> 5, c = (i & 31) << 2;
            *(float4*)&Ws[dd][c] = *(const float4*)(W + (size_t)(d0 + dd) * H + c);
        }
        __syncthreads();

        #pragma unroll
        for (int dd = 0; dd < 32; dd += 4) {
            float4 xr[4], wv[4];
            #pragma unroll
            for (int i = 0; i < 4; i++)
                xr[i] = *(const float4*)&Xs[(ty << 2) + i][dd];   // broadcast
            #pragma unroll
            for (int j = 0; j < 4; j++)
                wv[j] = *(const float4*)&Ws[dd + j][tx << 2];
            #pragma unroll
            for (int i = 0; i < 4; i++) {
                float xi[4] = {xr[i].x, xr[i].y, xr[i].z, xr[i].w};
                #pragma unroll
                for (int j = 0; j < 4; j++) {
                    acc[i][0] = fmaf(xi[j], wv[j].x, acc[i][0]);
                    acc[i][1] = fmaf(xi[j], wv[j].y, acc[i][1]);
                    acc[i][2] = fmaf(xi[j], wv[j].z, acc[i][2]);
                    acc[i][3] = fmaf(xi[j], wv[j].w, acc[i][3]);
                }
            }
        }
        __syncthreads();
    }

    #pragma unroll
    for (int i = 0; i < 4; i++) {
        float4 v = make_float4(acc[i][0], acc[i][1], acc[i][2], acc[i][3]);
        *(float4*)(Y + (size_t)(r0 + (ty << 2) + i) * H + (tx << 2)) = v;
    }
}

// ---------------------------------------------------------------------------
// Kernel 2: scores[b,q,k] = sum_h w[h] * tanh(qh[b,q,h] + kh[b,k,h])
// Work item = 32q x 32k tile, only for ktile < ceil(valid_len/32) (masked
// tails underflow to exact 0 in the reference softmax, so never needed).
// ~1060 items avg, pulled by 296 persistent CTAs via atomic counter ->
// near-perfect load balance. 256 threads, 2x2 reg tile; MUFU-bound by design
// (per hh per warp: 5 conflict-free LDS phases vs 32-cyc MUFU budget).
// ---------------------------------------------------------------------------
__global__ __launch_bounds__(256) void scores_kernel(
    const float* __restrict__ wv_g, const int* __restrict__ valid)
{
    __shared__ float qs[32][36];    // [q][h]  direct copy
    __shared__ float ks[32][33];    // [h][k]  transposed scatter
    __shared__ float wvs[H];
    __shared__ unsigned int s_item;

    int tid = threadIdx.x;
    if (tid < H) wvs[tid] = wv_g[tid];

    // Per-block item map: items_b = 8 qtiles * nk[b] ktiles
    int nk[BATCH], off[BATCH + 1];
    off[0] = 0;
    #pragma unroll
    for (int b = 0; b < BATCH; b++) {
        nk[b] = (valid[b] + 31) >> 5;
        off[b + 1] = off[b] + 8 * nk[b];
    }
    unsigned int total = (unsigned int)off[BATCH];

    int tx = tid & 15;      // 2 keys at 2*tx
    int ty = tid >> 4;      // 2 queries at 2*ty

    while (true) {
        __syncthreads();                      // smem reuse + s_item protection
        if (tid == 0) s_item = atomicAdd(&g_ctr, 1u);
        __syncthreads();
        unsigned int w = s_item;
        if (w >= total) break;

        int b = 0;
        #pragma unroll
        for (int bb = 0; bb < BATCH - 1; bb++)
            if (w >= (unsigned int)off[bb + 1]) b = bb + 1;
        int idx   = (int)w - off[b];
        int ktile = idx % nk[b];
        int qtile = idx / nk[b];
        int k0 = ktile << 5, q0 = qtile << 5;

        const float* qbase = g_qh + ((size_t)b * QLEN + q0) * H;
        const float* kbase = g_kh + ((size_t)b * KLEN + k0) * H;

        float acc[2][2] = {};

        for (int h0 = 0; h0 < H; h0 += 32) {
            __syncthreads();
            {
                int r = tid >> 3, hv = (tid & 7) << 2;
                float4 v = *(const float4*)(qbase + (size_t)r * H + h0 + hv);
                *(float4*)&qs[r][hv] = v;
                float4 u = *(const float4*)(kbase + (size_t)r * H + h0 + hv);
                ks[hv + 0][r] = u.x; ks[hv + 1][r] = u.y;
                ks[hv + 2][r] = u.z; ks[hv + 3][r] = u.w;
            }
            __syncthreads();

            #pragma unroll
            for (int hh = 0; hh < 32; hh++) {
                float w0 = wvs[h0 + hh];
                float qa = qs[(ty << 1) + 0][hh];
                float qb = qs[(ty << 1) + 1][hh];
                float ka = ks[hh][(tx << 1) + 0];
                float kb = ks[hh][(tx << 1) + 1];
                acc[0][0] = fmaf(w0, fast_tanh(qa + ka), acc[0][0]);
                acc[0][1] = fmaf(w0, fast_tanh(qa + kb), acc[0][1]);
                acc[1][0] = fmaf(w0, fast_tanh(qb + ka), acc[1][0]);
                acc[1][1] = fmaf(w0, fast_tanh(qb + kb), acc[1][1]);
            }
        }

        float* s0 = g_sc + ((size_t)b * QLEN + q0 + (ty << 1)) * KLEN + k0 + (tx << 1);
        *(float2*)s0          = make_float2(acc[0][0], acc[0][1]);
        *(float2*)(s0 + KLEN) = make_float2(acc[1][0], acc[1][1]);
    }
}

// ---------------------------------------------------------------------------
// Kernel 3: per (b,q) row masked softmax over k<valid_len, then attn @ V.
// 256 threads: 32 lanes x float4 over Dv=128, 8-way split over k.
// ---------------------------------------------------------------------------
__global__ __launch_bounds__(256) void softmax_av_kernel(
    const float* __restrict__ values, const int* __restrict__ valid,
    float* __restrict__ out)
{
    __shared__ float  p[KLEN];
    __shared__ float  red[8];
    __shared__ float4 accs[256];

    int bq  = blockIdx.x;
    int b   = bq >> 8;
    int vl  = valid[b];
    int tid = threadIdx.x;
    const float* srow = g_sc + (size_t)bq * KLEN;

    // --- max over valid scores ---
    float m = -3.0e38f;
    for (int k = tid; k < vl; k += 256) m = fmaxf(m, srow[k]);
    #pragma unroll
    for (int o = 16; o; o >>= 1) m = fmaxf(m, __shfl_xor_sync(0xffffffffu, m, o));
    if ((tid & 31) == 0) red[tid >> 5] = m;
    __syncthreads();
    m = red[0];
    #pragma unroll
    for (int g = 1; g < 8; g++) m = fmaxf(m, red[g]);

    // --- exp + sum ---
    float l = 0.f;
    for (int k = tid; k < vl; k += 256) {
        float e = __expf(srow[k] - m);
        p[k] = e;
        l += e;
    }
    #pragma unroll
    for (int o = 16; o; o >>= 1) l += __shfl_xor_sync(0xffffffffu, l, o);
    __syncthreads();                 // all reads of red(max) done
    if ((tid & 31) == 0) red[tid >> 5] = l;
    __syncthreads();                 // also makes p[] visible
    l = 0.f;
    #pragma unroll
    for (int g = 0; g < 8; g++) l += red[g];
    float inv = 1.0f / l;

    // --- attn @ V ---
    int vg = tid & 31;               // 4 v-columns at 4*vg
    int kg = tid >> 5;               // 8-way k split
    const float* vbase = values + (size_t)b * KLEN * DV + (vg << 2);
    float4 a = make_float4(0.f, 0.f, 0.f, 0.f);
    for (int k = kg; k < vl; k += 8) {
        float pk = p[k];
        float4 vv = *(const float4*)(vbase + (size_t)k * DV);
        a.x = fmaf(pk, vv.x, a.x);
        a.y = fmaf(pk, vv.y, a.y);
        a.z = fmaf(pk, vv.z, a.z);
        a.w = fmaf(pk, vv.w, a.w);
    }
    accs[tid] = a;
    __syncthreads();
    if (tid < 32) {
        float4 r = accs[tid];
        #pragma unroll
        for (int g = 1; g < 8; g++) {
            float4 t = accs[g * 32 + tid];
            r.x += t.x; r.y += t.y; r.z += t.z; r.w += t.w;
        }
        r.x *= inv; r.y *= inv; r.z *= inv; r.w *= inv;
        *(float4*)(out + (size_t)bq * DV + (tid << 2)) = r;
    }
}

// ---------------------------------------------------------------------------
extern "C" void kernel_launch(void* const* d_in, const int* in_sizes, int n_in,
                              void* d_out, int out_size)
{
    const float* queries = (const float*)d_in[0];
    const float* keys    = (const float*)d_in[1];
    const float* values  = (const float*)d_in[2];
    const int*   valid   = (const int*)d_in[3];
    const float* Wq      = (const float*)d_in[4];
    const float* Wk      = (const float*)d_in[5];
    const float* wv      = (const float*)d_in[6];
    float* out = (float*)d_out;

    proj_kernel<<<320, 256>>>(queries, keys, Wq, Wk);
    scores_kernel<<<296, 256>>>(wv, valid);
    softmax_av_kernel<<<BATCH * QLEN, 256>>>(values, valid, out);
}